// round 1
// baseline (speedup 1.0000x reference)
#include <cuda_runtime.h>
#include <cstdint>

#define N_NODES_MAX 100000
#define FDIM 256

// Scratch for support = X @ W  (102.4 MB, zero-init .bss — no runtime alloc)
__device__ float g_support[(size_t)N_NODES_MAX * FDIM];

// ---------------------------------------------------------------------------
// SGEMM: C[M,256] = A[M,256] @ B[256,256], fp32.
// Tile: BM=64, BN=64, BK=16, 256 threads, 4x4 microtile per thread.
// ---------------------------------------------------------------------------
__global__ __launch_bounds__(256) void gemm_kernel(const float* __restrict__ A,
                                                   const float* __restrict__ B,
                                                   int M) {
    __shared__ float As[16][65];  // [k][m], padded
    __shared__ float Bs[16][65];  // [k][n], padded

    const int tid = threadIdx.x;
    const int block_m = blockIdx.x * 64;
    const int block_n = blockIdx.y * 64;

    const int tx = tid & 15;        // n-tile index (0..15)
    const int ty = tid >> 4;        // m-tile index (0..15)

    float acc[4][4];
#pragma unroll
    for (int i = 0; i < 4; i++)
#pragma unroll
        for (int j = 0; j < 4; j++) acc[i][j] = 0.0f;

    // load indices
    const int a_row = tid >> 2;          // 0..63
    const int a_col4 = (tid & 3) * 4;    // 0,4,8,12
    const int b_k = tid >> 4;            // 0..15
    const int b_col4 = (tid & 15) * 4;   // 0..60

    for (int k0 = 0; k0 < FDIM; k0 += 16) {
        // Load A tile: 64 rows x 16 k, float4 per thread
        {
            int grow = block_m + a_row;
            float4 v = make_float4(0.f, 0.f, 0.f, 0.f);
            if (grow < M)
                v = *reinterpret_cast<const float4*>(A + (size_t)grow * FDIM + k0 + a_col4);
            As[a_col4 + 0][a_row] = v.x;
            As[a_col4 + 1][a_row] = v.y;
            As[a_col4 + 2][a_row] = v.z;
            As[a_col4 + 3][a_row] = v.w;
        }
        // Load B tile: 16 k x 64 n, float4 per thread
        {
            float4 v = *reinterpret_cast<const float4*>(B + (size_t)(k0 + b_k) * FDIM + block_n + b_col4);
            Bs[b_k][b_col4 + 0] = v.x;
            Bs[b_k][b_col4 + 1] = v.y;
            Bs[b_k][b_col4 + 2] = v.z;
            Bs[b_k][b_col4 + 3] = v.w;
        }
        __syncthreads();

#pragma unroll
        for (int kk = 0; kk < 16; kk++) {
            float a[4], b[4];
#pragma unroll
            for (int i = 0; i < 4; i++) a[i] = As[kk][ty * 4 + i];
#pragma unroll
            for (int j = 0; j < 4; j++) b[j] = Bs[kk][tx * 4 + j];
#pragma unroll
            for (int i = 0; i < 4; i++)
#pragma unroll
                for (int j = 0; j < 4; j++) acc[i][j] = fmaf(a[i], b[j], acc[i][j]);
        }
        __syncthreads();
    }

    // Store
#pragma unroll
    for (int i = 0; i < 4; i++) {
        int grow = block_m + ty * 4 + i;
        if (grow < M) {
            float4 v = make_float4(acc[i][0], acc[i][1], acc[i][2], acc[i][3]);
            *reinterpret_cast<float4*>(g_support + (size_t)grow * FDIM + block_n + tx * 4) = v;
        }
    }
}

// ---------------------------------------------------------------------------
// Init: out[n][j] = bias[j]
// ---------------------------------------------------------------------------
__global__ void init_bias_kernel(float* __restrict__ out,
                                 const float* __restrict__ bias,
                                 int total4) {
    int idx = blockIdx.x * blockDim.x + threadIdx.x;
    if (idx >= total4) return;
    // 64 float4 per row of 256
    const float4* b4 = reinterpret_cast<const float4*>(bias);
    float4 v = b4[idx & 63];
    reinterpret_cast<float4*>(out)[idx] = v;
}

// ---------------------------------------------------------------------------
// Edge scatter: out[r] += v * support[c], one warp per edge, 8 floats/thread.
// ---------------------------------------------------------------------------
__global__ __launch_bounds__(256) void spmm_edge_kernel(const int* __restrict__ rows,
                                                        const int* __restrict__ cols,
                                                        const float* __restrict__ vals,
                                                        float* __restrict__ out,
                                                        int E) {
    int warp = (blockIdx.x * blockDim.x + threadIdx.x) >> 5;
    int lane = threadIdx.x & 31;
    if (warp >= E) return;

    const int r = rows[warp];
    const int c = cols[warp];
    const float v = vals[warp];

    const float4* s = reinterpret_cast<const float4*>(g_support + (size_t)c * FDIM);
    float* o = out + (size_t)r * FDIM;

#pragma unroll
    for (int i = 0; i < 2; i++) {
        int e4 = lane + i * 32;           // 0..63
        float4 x = s[e4];
        int base = e4 * 4;
        atomicAdd(o + base + 0, x.x * v);
        atomicAdd(o + base + 1, x.y * v);
        atomicAdd(o + base + 2, x.z * v);
        atomicAdd(o + base + 3, x.w * v);
    }
}

extern "C" void kernel_launch(void* const* d_in, const int* in_sizes, int n_in,
                              void* d_out, int out_size) {
    const float* input  = (const float*)d_in[0];
    const float* weight = (const float*)d_in[1];
    const float* bias   = (const float*)d_in[2];
    const int*   e_rows = (const int*)d_in[3];
    const int*   e_cols = (const int*)d_in[4];
    const float* e_vals = (const float*)d_in[5];
    float* out = (float*)d_out;

    const int M = in_sizes[0] / FDIM;   // nodes
    const int E = in_sizes[3];          // edges

    // 1) support = X @ W
    dim3 ggrid((M + 63) / 64, FDIM / 64);
    gemm_kernel<<<ggrid, 256>>>(input, weight, M);

    // 2) out = bias (broadcast)
    int total4 = M * (FDIM / 4);
    init_bias_kernel<<<(total4 + 255) / 256, 256>>>(out, bias, total4);

    // 3) scatter edges
    long long threads = (long long)E * 32;
    int blocks = (int)((threads + 255) / 256);
    spmm_edge_kernel<<<blocks, 256>>>(e_rows, e_cols, e_vals, out, E);
}

// round 2
// speedup vs baseline: 3.6490x; 3.6490x over previous
#include <cuda_runtime.h>
#include <cstdint>

#define N_NODES_MAX 100032
#define FDIM 256
#define E_MAX 3300000
#define SCAN_B 1024

// ---- device scratch (static, no runtime alloc) ----
__device__ float g_support[(size_t)N_NODES_MAX * FDIM];   // X @ W
__device__ int   g_count[N_NODES_MAX];                    // per-row degree
__device__ int   g_start[N_NODES_MAX + 1];                // CSR row offsets
__device__ int   g_cursor[N_NODES_MAX];                   // scatter cursors
__device__ int   g_bsum[256];                             // scan block sums
__device__ int   g_boff[256];                             // scan block offsets
__device__ int   g_ecol[E_MAX];                           // CSR cols
__device__ float g_eval[E_MAX];                           // CSR vals

// ---------------------------------------------------------------------------
// SGEMM: support[M,256] = A[M,256] @ B[256,256]
// BM=128 BN=64 BK=16, 256 threads, 8x4 microtile.
// ---------------------------------------------------------------------------
__global__ __launch_bounds__(256) void gemm_kernel(const float* __restrict__ A,
                                                   const float* __restrict__ B,
                                                   int M) {
    __shared__ float As[16][128];  // [k][m]
    __shared__ float Bs[16][64];   // [k][n]

    const int tid = threadIdx.x;
    const int block_m = blockIdx.x * 128;
    const int block_n = blockIdx.y * 64;

    const int tx = tid & 15;   // col group -> cols tx*4..+3
    const int ty = tid >> 4;   // row group -> rows ty*8..+7

    float acc[8][4];
#pragma unroll
    for (int i = 0; i < 8; i++)
#pragma unroll
        for (int j = 0; j < 4; j++) acc[i][j] = 0.0f;

    for (int k0 = 0; k0 < FDIM; k0 += 16) {
        // A tile: 128 rows x 16 k = 512 float4, 2 per thread
#pragma unroll
        for (int i = 0; i < 2; i++) {
            int f = tid + i * 256;          // 0..511
            int row = f >> 2;               // 0..127
            int col4 = (f & 3) * 4;         // 0,4,8,12
            int grow = block_m + row;
            float4 v = make_float4(0.f, 0.f, 0.f, 0.f);
            if (grow < M)
                v = *reinterpret_cast<const float4*>(A + (size_t)grow * FDIM + k0 + col4);
            As[col4 + 0][row] = v.x;
            As[col4 + 1][row] = v.y;
            As[col4 + 2][row] = v.z;
            As[col4 + 3][row] = v.w;
        }
        // B tile: 16 k x 64 n = 256 float4, 1 per thread
        {
            int k = tid >> 4;
            int col4 = (tid & 15) * 4;
            float4 v = *reinterpret_cast<const float4*>(B + (size_t)(k0 + k) * FDIM + block_n + col4);
            Bs[k][col4 + 0] = v.x;
            Bs[k][col4 + 1] = v.y;
            Bs[k][col4 + 2] = v.z;
            Bs[k][col4 + 3] = v.w;
        }
        __syncthreads();

#pragma unroll
        for (int kk = 0; kk < 16; kk++) {
            float a[8], b[4];
#pragma unroll
            for (int i = 0; i < 8; i++) a[i] = As[kk][ty * 8 + i];
#pragma unroll
            for (int j = 0; j < 4; j++) b[j] = Bs[kk][tx * 4 + j];
#pragma unroll
            for (int i = 0; i < 8; i++)
#pragma unroll
                for (int j = 0; j < 4; j++) acc[i][j] = fmaf(a[i], b[j], acc[i][j]);
        }
        __syncthreads();
    }

#pragma unroll
    for (int i = 0; i < 8; i++) {
        int grow = block_m + ty * 8 + i;
        if (grow < M) {
            float4 v = make_float4(acc[i][0], acc[i][1], acc[i][2], acc[i][3]);
            *reinterpret_cast<float4*>(g_support + (size_t)grow * FDIM + block_n + tx * 4) = v;
        }
    }
}

// ---------------------------------------------------------------------------
// CSR build
// ---------------------------------------------------------------------------
__global__ void zero_counts_kernel(int M) {
    int i = blockIdx.x * blockDim.x + threadIdx.x;
    if (i < M) g_count[i] = 0;
}

__global__ void histogram_kernel(const int* __restrict__ rows, int E) {
    int i = blockIdx.x * blockDim.x + threadIdx.x;
    if (i < E) atomicAdd(&g_count[rows[i]], 1);
}

// pass 1: per-block (1024 elems) exclusive local prefix into g_start, block sum out
__global__ __launch_bounds__(SCAN_B) void scan1_kernel(int M) {
    __shared__ int wsum[32];
    int tid = threadIdx.x;
    int lane = tid & 31, wid = tid >> 5;
    int idx = blockIdx.x * SCAN_B + tid;
    int v = (idx < M) ? g_count[idx] : 0;
    int x = v;
#pragma unroll
    for (int off = 1; off < 32; off <<= 1) {
        int n = __shfl_up_sync(0xffffffffu, x, off);
        if (lane >= off) x += n;
    }
    if (lane == 31) wsum[wid] = x;
    __syncthreads();
    if (wid == 0) {
        int s = wsum[lane];
#pragma unroll
        for (int off = 1; off < 32; off <<= 1) {
            int n = __shfl_up_sync(0xffffffffu, s, off);
            if (lane >= off) s += n;
        }
        wsum[lane] = s;
    }
    __syncthreads();
    int woff = (wid > 0) ? wsum[wid - 1] : 0;
    if (idx < M) g_start[idx] = woff + x - v;   // exclusive within block
    if (tid == 0) g_bsum[blockIdx.x] = wsum[31];
}

// pass 2: exclusive scan of block sums (single thread; <=128 blocks)
__global__ void scan2_kernel(int nblocks) {
    if (threadIdx.x == 0 && blockIdx.x == 0) {
        int acc = 0;
        for (int b = 0; b < nblocks; b++) {
            g_boff[b] = acc;
            acc += g_bsum[b];
        }
    }
}

// pass 3: add block offsets, init cursors, set start[M]=E
__global__ __launch_bounds__(SCAN_B) void scan3_kernel(int M, int E) {
    int idx = blockIdx.x * SCAN_B + threadIdx.x;
    if (idx < M) {
        int s = g_start[idx] + g_boff[blockIdx.x];
        g_start[idx] = s;
        g_cursor[idx] = s;
    }
    if (idx == 0) g_start[M] = E;
}

__global__ void bucket_kernel(const int* __restrict__ rows,
                              const int* __restrict__ cols,
                              const float* __restrict__ vals, int E) {
    int i = blockIdx.x * blockDim.x + threadIdx.x;
    if (i >= E) return;
    int r = rows[i];
    int pos = atomicAdd(&g_cursor[r], 1);
    g_ecol[pos] = cols[i];
    g_eval[pos] = vals[i];
}

// ---------------------------------------------------------------------------
// Pull-mode SpMM: one 128-thread block per row; thread t owns float2 cols.
// out[r] = bias + sum_e val_e * support[col_e]
// ---------------------------------------------------------------------------
__global__ __launch_bounds__(128) void gather_kernel(const float* __restrict__ bias,
                                                     float* __restrict__ out) {
    const int r = blockIdx.x;
    const int t = threadIdx.x;

    const int s = g_start[r];
    const int e = g_start[r + 1];

    const float2* bias2 = reinterpret_cast<const float2*>(bias);
    float2 acc = bias2[t];

    const float2* sup2 = reinterpret_cast<const float2*>(g_support);

    for (int j = s; j < e; j++) {
        int c = __ldg(&g_ecol[j]);     // broadcast across block
        float v = __ldg(&g_eval[j]);
        float2 x = sup2[(size_t)c * 128 + t];
        acc.x = fmaf(v, x.x, acc.x);
        acc.y = fmaf(v, x.y, acc.y);
    }

    reinterpret_cast<float2*>(out)[(size_t)r * 128 + t] = acc;
}

extern "C" void kernel_launch(void* const* d_in, const int* in_sizes, int n_in,
                              void* d_out, int out_size) {
    const float* input  = (const float*)d_in[0];
    const float* weight = (const float*)d_in[1];
    const float* bias   = (const float*)d_in[2];
    const int*   e_rows = (const int*)d_in[3];
    const int*   e_cols = (const int*)d_in[4];
    const float* e_vals = (const float*)d_in[5];
    float* out = (float*)d_out;

    const int M = in_sizes[0] / FDIM;
    const int E = in_sizes[3];
    const int nscan = (M + SCAN_B - 1) / SCAN_B;

    // 1) support = X @ W
    dim3 ggrid((M + 127) / 128, FDIM / 64);
    gemm_kernel<<<ggrid, 256>>>(input, weight, M);

    // 2) CSR build (overlaps GEMM on the same stream order; independent data)
    zero_counts_kernel<<<(M + 255) / 256, 256>>>(M);
    histogram_kernel<<<(E + 255) / 256, 256>>>(e_rows, E);
    scan1_kernel<<<nscan, SCAN_B>>>(M);
    scan2_kernel<<<1, 32>>>(nscan);
    scan3_kernel<<<nscan, SCAN_B>>>(M, E);
    bucket_kernel<<<(E + 255) / 256, 256>>>(e_rows, e_cols, e_vals, E);

    // 3) pull-mode SpMM + bias
    gather_kernel<<<M, 128>>>(bias, out);
}

// round 3
// speedup vs baseline: 4.9740x; 1.3631x over previous
#include <cuda_runtime.h>
#include <cuda_fp16.h>
#include <cstdint>

#define N_NODES_MAX 100032
#define FDIM 256
#define E_MAX 3300000
#define SCAN_B 1024

// ---- device scratch (static .bss, no runtime alloc) ----
__device__ __half g_support_h[(size_t)N_NODES_MAX * FDIM];  // X @ W in fp16 (51 MB)
__device__ int    g_count[N_NODES_MAX];
__device__ int    g_start[N_NODES_MAX + 1];
__device__ int    g_cursor[N_NODES_MAX];
__device__ int    g_bsum[256];
__device__ int    g_boff[256];
__device__ int2   g_edge[E_MAX];                            // {col, val_bits} (26 MB)

// ---------------------------------------------------------------------------
// SGEMM (fp32 math, fp16 store): support[M,256] = A[M,256] @ B[256,256]
// BM=128 BN=64 BK=16, 256 threads, 8x4 microtile, double-buffered smem.
// ---------------------------------------------------------------------------
__global__ __launch_bounds__(256) void gemm_kernel(const float* __restrict__ A,
                                                   const float* __restrict__ B,
                                                   int M) {
    __shared__ float As[2][16][128];  // [buf][k][m]
    __shared__ float Bs[2][16][64];   // [buf][k][n]

    const int tid = threadIdx.x;
    const int block_m = blockIdx.x * 128;
    const int block_n = blockIdx.y * 64;

    const int tx = tid & 15;   // cols tx*4..+3
    const int ty = tid >> 4;   // rows ty*8..+7

    // loader indices
    const int a_row0 = tid >> 2;            // 0..63  (plus +64 for second float4)
    const int a_col4 = (tid & 3) * 4;       // 0,4,8,12
    const int b_k = tid >> 4;               // 0..15
    const int b_col4 = (tid & 15) * 4;      // 0..60

    float acc[8][4];
#pragma unroll
    for (int i = 0; i < 8; i++)
#pragma unroll
        for (int j = 0; j < 4; j++) acc[i][j] = 0.0f;

    // load tile 0
    {
#pragma unroll
        for (int i = 0; i < 2; i++) {
            int row = a_row0 + i * 64;
            int grow = block_m + row;
            float4 v = make_float4(0.f, 0.f, 0.f, 0.f);
            if (grow < M)
                v = *reinterpret_cast<const float4*>(A + (size_t)grow * FDIM + a_col4);
            As[0][a_col4 + 0][row] = v.x;
            As[0][a_col4 + 1][row] = v.y;
            As[0][a_col4 + 2][row] = v.z;
            As[0][a_col4 + 3][row] = v.w;
        }
        float4 v = *reinterpret_cast<const float4*>(B + (size_t)b_k * FDIM + block_n + b_col4);
        Bs[0][b_k][b_col4 + 0] = v.x;
        Bs[0][b_k][b_col4 + 1] = v.y;
        Bs[0][b_k][b_col4 + 2] = v.z;
        Bs[0][b_k][b_col4 + 3] = v.w;
    }
    __syncthreads();

    int buf = 0;
    for (int k0 = 0; k0 < FDIM; k0 += 16) {
        const bool has_next = (k0 + 16 < FDIM);
        float4 aR[2];
        float4 bR;
        if (has_next) {
#pragma unroll
            for (int i = 0; i < 2; i++) {
                int grow = block_m + a_row0 + i * 64;
                aR[i] = make_float4(0.f, 0.f, 0.f, 0.f);
                if (grow < M)
                    aR[i] = *reinterpret_cast<const float4*>(A + (size_t)grow * FDIM + k0 + 16 + a_col4);
            }
            bR = *reinterpret_cast<const float4*>(B + (size_t)(k0 + 16 + b_k) * FDIM + block_n + b_col4);
        }

#pragma unroll
        for (int kk = 0; kk < 16; kk++) {
            float a[8], b[4];
#pragma unroll
            for (int i = 0; i < 8; i++) a[i] = As[buf][kk][ty * 8 + i];
#pragma unroll
            for (int j = 0; j < 4; j++) b[j] = Bs[buf][kk][tx * 4 + j];
#pragma unroll
            for (int i = 0; i < 8; i++)
#pragma unroll
                for (int j = 0; j < 4; j++) acc[i][j] = fmaf(a[i], b[j], acc[i][j]);
        }

        if (has_next) {
            int nb = buf ^ 1;
#pragma unroll
            for (int i = 0; i < 2; i++) {
                int row = a_row0 + i * 64;
                As[nb][a_col4 + 0][row] = aR[i].x;
                As[nb][a_col4 + 1][row] = aR[i].y;
                As[nb][a_col4 + 2][row] = aR[i].z;
                As[nb][a_col4 + 3][row] = aR[i].w;
            }
            Bs[nb][b_k][b_col4 + 0] = bR.x;
            Bs[nb][b_k][b_col4 + 1] = bR.y;
            Bs[nb][b_k][b_col4 + 2] = bR.z;
            Bs[nb][b_k][b_col4 + 3] = bR.w;
            __syncthreads();
            buf = nb;
        }
    }

    // store fp16
#pragma unroll
    for (int i = 0; i < 8; i++) {
        int grow = block_m + ty * 8 + i;
        if (grow < M) {
            __half2 p0 = __floats2half2_rn(acc[i][0], acc[i][1]);
            __half2 p1 = __floats2half2_rn(acc[i][2], acc[i][3]);
            uint2 pack;
            pack.x = *reinterpret_cast<uint32_t*>(&p0);
            pack.y = *reinterpret_cast<uint32_t*>(&p1);
            *reinterpret_cast<uint2*>(g_support_h + (size_t)grow * FDIM + block_n + tx * 4) = pack;
        }
    }
}

// ---------------------------------------------------------------------------
// CSR build
// ---------------------------------------------------------------------------
__global__ void zero_counts_kernel(int M) {
    int i = blockIdx.x * blockDim.x + threadIdx.x;
    if (i < M) g_count[i] = 0;
}

__global__ void histogram_kernel(const int* __restrict__ rows, int E) {
    int i = blockIdx.x * blockDim.x + threadIdx.x;
    if (i < E) atomicAdd(&g_count[rows[i]], 1);
}

__global__ __launch_bounds__(SCAN_B) void scan1_kernel(int M) {
    __shared__ int wsum[32];
    int tid = threadIdx.x;
    int lane = tid & 31, wid = tid >> 5;
    int idx = blockIdx.x * SCAN_B + tid;
    int v = (idx < M) ? g_count[idx] : 0;
    int x = v;
#pragma unroll
    for (int off = 1; off < 32; off <<= 1) {
        int n = __shfl_up_sync(0xffffffffu, x, off);
        if (lane >= off) x += n;
    }
    if (lane == 31) wsum[wid] = x;
    __syncthreads();
    if (wid == 0) {
        int s = wsum[lane];
#pragma unroll
        for (int off = 1; off < 32; off <<= 1) {
            int n = __shfl_up_sync(0xffffffffu, s, off);
            if (lane >= off) s += n;
        }
        wsum[lane] = s;
    }
    __syncthreads();
    int woff = (wid > 0) ? wsum[wid - 1] : 0;
    if (idx < M) g_start[idx] = woff + x - v;
    if (tid == 0) g_bsum[blockIdx.x] = wsum[31];
}

__global__ void scan2_kernel(int nblocks) {
    if (threadIdx.x == 0 && blockIdx.x == 0) {
        int acc = 0;
        for (int b = 0; b < nblocks; b++) {
            g_boff[b] = acc;
            acc += g_bsum[b];
        }
    }
}

__global__ __launch_bounds__(SCAN_B) void scan3_kernel(int M, int E) {
    int idx = blockIdx.x * SCAN_B + threadIdx.x;
    if (idx < M) {
        int s = g_start[idx] + g_boff[blockIdx.x];
        g_start[idx] = s;
        g_cursor[idx] = s;
    }
    if (idx == 0) g_start[M] = E;
}

__global__ void bucket_kernel(const int* __restrict__ rows,
                              const int* __restrict__ cols,
                              const float* __restrict__ vals, int E) {
    int i = blockIdx.x * blockDim.x + threadIdx.x;
    if (i >= E) return;
    int r = rows[i];
    int pos = atomicAdd(&g_cursor[r], 1);
    g_edge[pos] = make_int2(cols[i], __float_as_int(vals[i]));
}

// ---------------------------------------------------------------------------
// Pull-mode SpMM: one warp per row; lane owns 8 halfs (16B load).
// out[r] = bias + sum_e val_e * support[col_e]
// ---------------------------------------------------------------------------
__global__ __launch_bounds__(256) void gather_kernel(const float* __restrict__ bias,
                                                     float* __restrict__ out, int M) {
    const int warp = (blockIdx.x * 256 + threadIdx.x) >> 5;
    const int lane = threadIdx.x & 31;
    if (warp >= M) return;
    const int r = warp;

    const int s = g_start[r];
    const int e = g_start[r + 1];

    const float4* bias4 = reinterpret_cast<const float4*>(bias);
    float4 a0 = bias4[lane * 2];
    float4 a1 = bias4[lane * 2 + 1];

    const uint4* sup = reinterpret_cast<const uint4*>(g_support_h);  // 32 uint4 per row

    int2 nxt = (s < e) ? __ldg(&g_edge[s]) : make_int2(0, 0);
    for (int j = s; j < e; j++) {
        const int2 cur = nxt;
        if (j + 1 < e) nxt = __ldg(&g_edge[j + 1]);
        const float v = __int_as_float(cur.y);
        uint4 h = __ldg(&sup[(size_t)cur.x * 32 + lane]);

        float2 f0 = __half22float2(*reinterpret_cast<__half2*>(&h.x));
        float2 f1 = __half22float2(*reinterpret_cast<__half2*>(&h.y));
        float2 f2 = __half22float2(*reinterpret_cast<__half2*>(&h.z));
        float2 f3 = __half22float2(*reinterpret_cast<__half2*>(&h.w));

        a0.x = fmaf(v, f0.x, a0.x);
        a0.y = fmaf(v, f0.y, a0.y);
        a0.z = fmaf(v, f1.x, a0.z);
        a0.w = fmaf(v, f1.y, a0.w);
        a1.x = fmaf(v, f2.x, a1.x);
        a1.y = fmaf(v, f2.y, a1.y);
        a1.z = fmaf(v, f3.x, a1.z);
        a1.w = fmaf(v, f3.y, a1.w);
    }

    float4* out4 = reinterpret_cast<float4*>(out);
    out4[(size_t)r * 64 + lane * 2] = a0;
    out4[(size_t)r * 64 + lane * 2 + 1] = a1;
}

extern "C" void kernel_launch(void* const* d_in, const int* in_sizes, int n_in,
                              void* d_out, int out_size) {
    const float* input  = (const float*)d_in[0];
    const float* weight = (const float*)d_in[1];
    const float* bias   = (const float*)d_in[2];
    const int*   e_rows = (const int*)d_in[3];
    const int*   e_cols = (const int*)d_in[4];
    const float* e_vals = (const float*)d_in[5];
    float* out = (float*)d_out;

    const int M = in_sizes[0] / FDIM;
    const int E = in_sizes[3];
    const int nscan = (M + SCAN_B - 1) / SCAN_B;

    // 1) support = X @ W  (fp16 out)
    dim3 ggrid((M + 127) / 128, FDIM / 64);
    gemm_kernel<<<ggrid, 256>>>(input, weight, M);

    // 2) CSR build
    zero_counts_kernel<<<(M + 255) / 256, 256>>>(M);
    histogram_kernel<<<(E + 255) / 256, 256>>>(e_rows, E);
    scan1_kernel<<<nscan, SCAN_B>>>(M);
    scan2_kernel<<<1, 32>>>(nscan);
    scan3_kernel<<<nscan, SCAN_B>>>(M, E);
    bucket_kernel<<<(E + 255) / 256, 256>>>(e_rows, e_cols, e_vals, E);

    // 3) pull-mode SpMM + bias
    gather_kernel<<<(M * 32 + 255) / 256, 256>>>(bias, out, M);
}

// round 4
// speedup vs baseline: 6.5361x; 1.3140x over previous
#include <cuda_runtime.h>
#include <cuda_fp16.h>
#include <mma.h>
#include <cstdint>

using namespace nvcuda;

#define N_NODES_MAX 100032
#define FDIM 256
#define E_MAX 3300000
#define SCAN_B 1024

// ---- device scratch (static .bss, no runtime alloc) ----
__device__ __half g_support_h[(size_t)N_NODES_MAX * FDIM];  // X @ W in fp16 (51 MB)
__device__ int    g_count[N_NODES_MAX];
__device__ int    g_start[N_NODES_MAX + 1];
__device__ int    g_cursor[N_NODES_MAX];
__device__ int    g_bsum[256];
__device__ int    g_boff[256];
__device__ int2   g_edge[E_MAX];                            // {col, val_bits} (26 MB)

// ---------------------------------------------------------------------------
// tf32 WMMA GEMM: support[M,256] = A[M,256] @ B[256,256], fp16 store.
// BM=128 BN=128 BK=32, 256 threads (8 warps: 4 in m x 2 in n).
// Warp tile 32(m) x 64(n) = 2x4 wmma 16x16x8 fragments.
// ---------------------------------------------------------------------------
__global__ __launch_bounds__(256) void gemm_tf32_kernel(const float* __restrict__ A,
                                                        const float* __restrict__ B,
                                                        int M) {
    __shared__ float As[128][36];        // [m][k], stride 36 (144B, 16B-aligned rows)
    __shared__ float Bs[32][136];        // [k][n], stride 136 (544B)
    __shared__ float Cstage[8][16][20];  // per-warp epilogue staging (ldm=20, mult of 4)

    const int tid = threadIdx.x;
    const int wid = tid >> 5;
    const int lane = tid & 31;
    const int warp_m = wid & 3;   // 0..3 -> m offset warp_m*32
    const int warp_n = wid >> 2;  // 0..1 -> n offset warp_n*64
    const int block_m = blockIdx.x * 128;
    const int block_n = blockIdx.y * 128;

    wmma::fragment<wmma::accumulator, 16, 16, 8, float> c[2][4];
#pragma unroll
    for (int i = 0; i < 2; i++)
#pragma unroll
        for (int j = 0; j < 4; j++) wmma::fill_fragment(c[i][j], 0.0f);

    for (int k0 = 0; k0 < FDIM; k0 += 32) {
        __syncthreads();
        // A tile: 128 x 32 floats = 1024 float4, 4 per thread
#pragma unroll
        for (int i = 0; i < 4; i++) {
            int f = tid + i * 256;
            int row = f >> 3;             // 0..127
            int col4 = (f & 7) * 4;       // 0..28
            int grow = block_m + row;
            float4 v = make_float4(0.f, 0.f, 0.f, 0.f);
            if (grow < M)
                v = *reinterpret_cast<const float4*>(A + (size_t)grow * FDIM + k0 + col4);
            v.x = wmma::__float_to_tf32(v.x);
            v.y = wmma::__float_to_tf32(v.y);
            v.z = wmma::__float_to_tf32(v.z);
            v.w = wmma::__float_to_tf32(v.w);
            *reinterpret_cast<float4*>(&As[row][col4]) = v;
        }
        // B tile: 32 x 128 floats = 1024 float4, 4 per thread
#pragma unroll
        for (int i = 0; i < 4; i++) {
            int f = tid + i * 256;
            int row = f >> 5;             // 0..31 (k)
            int col4 = (f & 31) * 4;      // 0..124
            float4 v = *reinterpret_cast<const float4*>(B + (size_t)(k0 + row) * FDIM + block_n + col4);
            v.x = wmma::__float_to_tf32(v.x);
            v.y = wmma::__float_to_tf32(v.y);
            v.z = wmma::__float_to_tf32(v.z);
            v.w = wmma::__float_to_tf32(v.w);
            *reinterpret_cast<float4*>(&Bs[row][col4]) = v;
        }
        __syncthreads();

#pragma unroll
        for (int ks = 0; ks < 4; ks++) {
            wmma::fragment<wmma::matrix_a, 16, 16, 8, wmma::precision::tf32, wmma::row_major> a[2];
            wmma::fragment<wmma::matrix_b, 16, 16, 8, wmma::precision::tf32, wmma::row_major> b[4];
#pragma unroll
            for (int i = 0; i < 2; i++)
                wmma::load_matrix_sync(a[i], &As[warp_m * 32 + i * 16][ks * 8], 36);
#pragma unroll
            for (int j = 0; j < 4; j++)
                wmma::load_matrix_sync(b[j], &Bs[ks * 8][warp_n * 64 + j * 16], 136);
#pragma unroll
            for (int i = 0; i < 2; i++)
#pragma unroll
                for (int j = 0; j < 4; j++)
                    wmma::mma_sync(c[i][j], a[i], b[j], c[i][j]);
        }
    }

    // Epilogue: stage each 16x16 fragment in smem, convert to fp16, store.
#pragma unroll
    for (int i = 0; i < 2; i++) {
#pragma unroll
        for (int j = 0; j < 4; j++) {
            __syncwarp();
            wmma::store_matrix_sync(&Cstage[wid][0][0], c[i][j], 20, wmma::mem_row_major);
            __syncwarp();
            int r = lane >> 1;
            int half8 = (lane & 1) * 8;
            int grow = block_m + warp_m * 32 + i * 16 + r;
            int gcol = block_n + warp_n * 64 + j * 16 + half8;
            if (grow < M) {
                const float* src = &Cstage[wid][r][half8];
                __half2 h0 = __floats2half2_rn(src[0], src[1]);
                __half2 h1 = __floats2half2_rn(src[2], src[3]);
                __half2 h2 = __floats2half2_rn(src[4], src[5]);
                __half2 h3 = __floats2half2_rn(src[6], src[7]);
                uint4 pack;
                pack.x = *reinterpret_cast<uint32_t*>(&h0);
                pack.y = *reinterpret_cast<uint32_t*>(&h1);
                pack.z = *reinterpret_cast<uint32_t*>(&h2);
                pack.w = *reinterpret_cast<uint32_t*>(&h3);
                *reinterpret_cast<uint4*>(g_support_h + (size_t)grow * FDIM + gcol) = pack;
            }
        }
    }
}

// ---------------------------------------------------------------------------
// CSR build
// ---------------------------------------------------------------------------
__global__ void zero_counts_kernel(int M) {
    int i = blockIdx.x * blockDim.x + threadIdx.x;
    if (i < M) g_count[i] = 0;
}

__global__ void histogram_kernel(const int* __restrict__ rows, int E) {
    int i = blockIdx.x * blockDim.x + threadIdx.x;
    if (i < E) atomicAdd(&g_count[rows[i]], 1);
}

__global__ __launch_bounds__(SCAN_B) void scan1_kernel(int M) {
    __shared__ int wsum[32];
    int tid = threadIdx.x;
    int lane = tid & 31, wid = tid >> 5;
    int idx = blockIdx.x * SCAN_B + tid;
    int v = (idx < M) ? g_count[idx] : 0;
    int x = v;
#pragma unroll
    for (int off = 1; off < 32; off <<= 1) {
        int n = __shfl_up_sync(0xffffffffu, x, off);
        if (lane >= off) x += n;
    }
    if (lane == 31) wsum[wid] = x;
    __syncthreads();
    if (wid == 0) {
        int s = wsum[lane];
#pragma unroll
        for (int off = 1; off < 32; off <<= 1) {
            int n = __shfl_up_sync(0xffffffffu, s, off);
            if (lane >= off) s += n;
        }
        wsum[lane] = s;
    }
    __syncthreads();
    int woff = (wid > 0) ? wsum[wid - 1] : 0;
    if (idx < M) g_start[idx] = woff + x - v;
    if (tid == 0) g_bsum[blockIdx.x] = wsum[31];
}

__global__ void scan2_kernel(int nblocks) {
    if (threadIdx.x == 0 && blockIdx.x == 0) {
        int acc = 0;
        for (int b = 0; b < nblocks; b++) {
            g_boff[b] = acc;
            acc += g_bsum[b];
        }
    }
}

__global__ __launch_bounds__(SCAN_B) void scan3_kernel(int M, int E) {
    int idx = blockIdx.x * SCAN_B + threadIdx.x;
    if (idx < M) {
        int s = g_start[idx] + g_boff[blockIdx.x];
        g_start[idx] = s;
        g_cursor[idx] = s;
    }
    if (idx == 0) g_start[M] = E;
}

__global__ void bucket_kernel(const int* __restrict__ rows,
                              const int* __restrict__ cols,
                              const float* __restrict__ vals, int E) {
    int i = blockIdx.x * blockDim.x + threadIdx.x;
    if (i >= E) return;
    int r = rows[i];
    int pos = atomicAdd(&g_cursor[r], 1);
    g_edge[pos] = make_int2(cols[i], __float_as_int(vals[i]));
}

// ---------------------------------------------------------------------------
// Pull-mode SpMM: one warp per row; lane owns 8 halfs (16B load).
// ---------------------------------------------------------------------------
__global__ __launch_bounds__(256) void gather_kernel(const float* __restrict__ bias,
                                                     float* __restrict__ out, int M) {
    const int warp = (blockIdx.x * 256 + threadIdx.x) >> 5;
    const int lane = threadIdx.x & 31;
    if (warp >= M) return;
    const int r = warp;

    const int s = g_start[r];
    const int e = g_start[r + 1];

    const float4* bias4 = reinterpret_cast<const float4*>(bias);
    float4 a0 = bias4[lane * 2];
    float4 a1 = bias4[lane * 2 + 1];

    const uint4* sup = reinterpret_cast<const uint4*>(g_support_h);  // 32 uint4 per row

    int2 nxt = (s < e) ? __ldg(&g_edge[s]) : make_int2(0, 0);
    for (int j = s; j < e; j++) {
        const int2 cur = nxt;
        if (j + 1 < e) nxt = __ldg(&g_edge[j + 1]);
        const float v = __int_as_float(cur.y);
        uint4 h = __ldg(&sup[(size_t)cur.x * 32 + lane]);

        float2 f0 = __half22float2(*reinterpret_cast<__half2*>(&h.x));
        float2 f1 = __half22float2(*reinterpret_cast<__half2*>(&h.y));
        float2 f2 = __half22float2(*reinterpret_cast<__half2*>(&h.z));
        float2 f3 = __half22float2(*reinterpret_cast<__half2*>(&h.w));

        a0.x = fmaf(v, f0.x, a0.x);
        a0.y = fmaf(v, f0.y, a0.y);
        a0.z = fmaf(v, f1.x, a0.z);
        a0.w = fmaf(v, f1.y, a0.w);
        a1.x = fmaf(v, f2.x, a1.x);
        a1.y = fmaf(v, f2.y, a1.y);
        a1.z = fmaf(v, f3.x, a1.z);
        a1.w = fmaf(v, f3.y, a1.w);
    }

    float4* out4 = reinterpret_cast<float4*>(out);
    out4[(size_t)r * 64 + lane * 2] = a0;
    out4[(size_t)r * 64 + lane * 2 + 1] = a1;
}

extern "C" void kernel_launch(void* const* d_in, const int* in_sizes, int n_in,
                              void* d_out, int out_size) {
    const float* input  = (const float*)d_in[0];
    const float* weight = (const float*)d_in[1];
    const float* bias   = (const float*)d_in[2];
    const int*   e_rows = (const int*)d_in[3];
    const int*   e_cols = (const int*)d_in[4];
    const float* e_vals = (const float*)d_in[5];
    float* out = (float*)d_out;

    const int M = in_sizes[0] / FDIM;
    const int E = in_sizes[3];
    const int nscan = (M + SCAN_B - 1) / SCAN_B;

    // 1) support = X @ W  (tf32 tensor cores, fp16 out)
    dim3 ggrid((M + 127) / 128, FDIM / 128);
    gemm_tf32_kernel<<<ggrid, 256>>>(input, weight, M);

    // 2) CSR build
    zero_counts_kernel<<<(M + 255) / 256, 256>>>(M);
    histogram_kernel<<<(E + 255) / 256, 256>>>(e_rows, E);
    scan1_kernel<<<nscan, SCAN_B>>>(M);
    scan2_kernel<<<1, 32>>>(nscan);
    scan3_kernel<<<nscan, SCAN_B>>>(M, E);
    bucket_kernel<<<(E + 255) / 256, 256>>>(e_rows, e_cols, e_vals, E);

    // 3) pull-mode SpMM + bias
    gather_kernel<<<(M * 32 + 255) / 256, 256>>>(bias, out, M);
}